// round 2
// baseline (speedup 1.0000x reference)
#include <cuda_runtime.h>
#include <cuda_fp16.h>
#include <cstdint>

// ---------------------------------------------------------------------------
// Problem constants
// ---------------------------------------------------------------------------
#define SIG_LEN     262144
#define NFFT        1024
#define HOP         256
#define PADV        512
#define PADDED_LEN  (SIG_LEN + NFFT)      // 263168
#define BATCH       16
#define F_BINS      513
#define N_FRAMES    1025
#define N_CH        1026
#define NPAD        1032                  // padded N for transposed kernel rows

// GEMM tiling
#define BM 128
#define BN 128
#define BK 32
#define KITERS (NFFT / BK)                // 32
#define STAGES 4

// SMEM layout (halves). A rows padded to 40 (80 B), B rows padded to 136 (272 B)
#define A_STRIDE 40
#define B_STRIDE 136
#define A_STAGE_BYTES (BM * A_STRIDE * 2)          // 10240
#define B_STAGE_BYTES (BK * B_STRIDE * 2)          // 8704
#define STAGE_BYTES   (A_STAGE_BYTES + B_STAGE_BYTES)  // 18944
#define SMEM_TOTAL    (STAGES * STAGE_BYTES)       // 75776

// ---------------------------------------------------------------------------
// Device scratch (allocation-free rule: static __device__ arrays)
// ---------------------------------------------------------------------------
__device__ __half g_sig16[BATCH * PADDED_LEN];   // reflect-padded fp16 signal
__device__ __half g_kerT16[NFFT * NPAD];         // transposed fp16 DFT kernel [k][c'=2f+ri]

// ---------------------------------------------------------------------------
// PTX helpers (sm_100-safe: cp.async / ldmatrix / mma.sync only)
// ---------------------------------------------------------------------------
__device__ __forceinline__ uint32_t smem_to_u32(const void* p) {
    uint32_t a;
    asm("{ .reg .u64 t; cvta.to.shared.u64 t, %1; cvt.u32.u64 %0, t; }"
        : "=r"(a) : "l"(p));
    return a;
}

__device__ __forceinline__ void cp_async16(uint32_t dst, const void* src) {
    asm volatile("cp.async.cg.shared.global [%0], [%1], 16;" :: "r"(dst), "l"(src));
}
#define CP_COMMIT() asm volatile("cp.async.commit_group;" ::: "memory")
#define CP_WAIT(N)  asm volatile("cp.async.wait_group %0;" :: "n"(N) : "memory")

__device__ __forceinline__ void ldmatrix_x4(uint32_t* r, uint32_t addr) {
    asm volatile("ldmatrix.sync.aligned.m8n8.x4.shared.b16 {%0,%1,%2,%3}, [%4];"
                 : "=r"(r[0]), "=r"(r[1]), "=r"(r[2]), "=r"(r[3]) : "r"(addr));
}
__device__ __forceinline__ void ldmatrix_x4_t(uint32_t* r, uint32_t addr) {
    asm volatile("ldmatrix.sync.aligned.m8n8.x4.trans.shared.b16 {%0,%1,%2,%3}, [%4];"
                 : "=r"(r[0]), "=r"(r[1]), "=r"(r[2]), "=r"(r[3]) : "r"(addr));
}
__device__ __forceinline__ void mma_16816(float* c, const uint32_t* a, const uint32_t* b) {
    asm volatile(
        "mma.sync.aligned.m16n8k16.row.col.f32.f16.f16.f32 "
        "{%0,%1,%2,%3}, {%4,%5,%6,%7}, {%8,%9}, {%0,%1,%2,%3};"
        : "+f"(c[0]), "+f"(c[1]), "+f"(c[2]), "+f"(c[3])
        : "r"(a[0]), "r"(a[1]), "r"(a[2]), "r"(a[3]), "r"(b[0]), "r"(b[1]));
}

// ---------------------------------------------------------------------------
// Reflect padding helper
// ---------------------------------------------------------------------------
__device__ __forceinline__ int reflect_idx(int j) {
    int idx = j - PADV;
    idx = (idx < 0) ? -idx : idx;
    idx = (idx >= SIG_LEN) ? (2 * SIG_LEN - 2 - idx) : idx;
    return idx;
}

// ---------------------------------------------------------------------------
// Prologue: fp16 conversions
// ---------------------------------------------------------------------------
__global__ void pad_convert_kernel(const float* __restrict__ sig) {
    int i = blockIdx.x * blockDim.x + threadIdx.x;
    if (i >= BATCH * PADDED_LEN) return;
    int b = i / PADDED_LEN;
    int j = i - b * PADDED_LEN;
    g_sig16[i] = __float2half(sig[(size_t)b * SIG_LEN + reflect_idx(j)]);
}

// transpose + permute kernel: g_kerT16[k][c'] with c' = 2f + ri
__global__ void ker_convert_kernel(const float* __restrict__ ker) {
    int i = blockIdx.x * blockDim.x + threadIdx.x;
    if (i >= NFFT * N_CH) return;
    int k  = i / N_CH;
    int cp = i - k * N_CH;
    int f  = cp >> 1;
    int ri = cp & 1;
    g_kerT16[k * NPAD + cp] =
        __float2half(ker[((size_t)(ri * F_BINS + f)) * NFFT + k]);
}

// ---------------------------------------------------------------------------
// Cleanup kernels (fp32 exact): last frame t=1024, last bin f=512
// ---------------------------------------------------------------------------
__global__ void cleanup_last_frame(const float* __restrict__ sig,
                                   const float* __restrict__ ker,
                                   float* __restrict__ out) {
    int w  = threadIdx.x >> 5, l = threadIdx.x & 31;
    int cp = blockIdx.x * 8 + w;        // c' < 1024
    int b  = blockIdx.y;
    int f  = cp >> 1, ri = cp & 1;
    const float* kr = ker + ((size_t)(ri * F_BINS + f)) * NFFT;
    const float* sg = sig + (size_t)b * SIG_LEN;
    float s = 0.f;
    const int base = 1024 * HOP;
    #pragma unroll 8
    for (int q = 0; q < 32; ++q) {
        int k = l + q * 32;
        s += sg[reflect_idx(base + k)] * kr[k];
    }
    #pragma unroll
    for (int o = 16; o; o >>= 1) s += __shfl_xor_sync(0xffffffffu, s, o);
    if (l == 0)
        out[(((size_t)b * F_BINS + f) * N_FRAMES + 1024) * 2 + ri] = s;
}

__global__ void cleanup_last_bin(const float* __restrict__ sig,
                                 const float* __restrict__ ker,
                                 float* __restrict__ out) {
    int ri = threadIdx.x >> 5, l = threadIdx.x & 31;
    int t  = blockIdx.x;
    int b  = blockIdx.y;
    const float* kr = ker + ((size_t)(ri * F_BINS + 512)) * NFFT;
    const float* sg = sig + (size_t)b * SIG_LEN;
    float s = 0.f;
    const int base = t * HOP;
    #pragma unroll 8
    for (int q = 0; q < 32; ++q) {
        int k = l + q * 32;
        s += sg[reflect_idx(base + k)] * kr[k];
    }
    #pragma unroll
    for (int o = 16; o; o >>= 1) s += __shfl_xor_sync(0xffffffffu, s, o);
    if (l == 0)
        out[(((size_t)b * F_BINS + 512) * N_FRAMES + t) * 2 + ri] = s;
}

// ---------------------------------------------------------------------------
// Main GEMM: mma.sync fp16, cp.async 4-stage pipeline
//   grid = (8 n-tiles, 8 m-tiles, 16 batches), block = 256 threads
//   warp grid 2(M) x 4(N), warp tile 64 x 32
// ---------------------------------------------------------------------------
__global__ void __launch_bounds__(256, 2) stft_gemm(float* __restrict__ out) {
    extern __shared__ __half smem[];
    const uint32_t sb = smem_to_u32(smem);
    const int tid = threadIdx.x;
    const int wid = tid >> 5;
    const int lane = tid & 31;
    const int n0 = blockIdx.x * BN;
    const int m0 = blockIdx.y * BM;
    const int b  = blockIdx.z;

    const __half* gA = g_sig16 + (size_t)b * PADDED_LEN;  // frame t -> t*HOP

    // per-thread cp.async assignments (2 A-chunks + 2 B-chunks per stage)
    const int aq0 = tid, aq1 = tid + 256;     // A chunk ids (512 total)
    const int ar0 = aq0 >> 2, ac0 = aq0 & 3;
    const int ar1 = aq1 >> 2, ac1 = aq1 & 3;
    const int br0 = aq0 >> 4, bc0 = aq0 & 15; // B chunk ids (512 total)
    const int br1 = aq1 >> 4, bc1 = aq1 & 15;

    // ldmatrix lane decomposition
    const int lm   = lane >> 3;            // matrix index 0..3
    const int l7   = lane & 7;
    const int row8 = (lm & 1) * 8 + l7;    // row/krow within 16
    const int off8 = (lm >> 1) * 8;        // col offset within 16

    const int warp_m = wid & 1;            // 0..1
    const int warp_n = wid >> 1;           // 0..3

    float acc[4][4][4];
    #pragma unroll
    for (int i = 0; i < 4; ++i)
        #pragma unroll
        for (int j = 0; j < 4; ++j)
            #pragma unroll
            for (int v = 0; v < 4; ++v) acc[i][j][v] = 0.f;

    // ---- stage loader ----
    auto load_stage = [&](int s, int k0) {
        const uint32_t as = sb + s * STAGE_BYTES;
        const uint32_t bs = as + A_STAGE_BYTES;
        cp_async16(as + (ar0 * A_STRIDE + ac0 * 8) * 2,
                   gA + (size_t)(m0 + ar0) * HOP + k0 + ac0 * 8);
        cp_async16(as + (ar1 * A_STRIDE + ac1 * 8) * 2,
                   gA + (size_t)(m0 + ar1) * HOP + k0 + ac1 * 8);
        cp_async16(bs + (br0 * B_STRIDE + bc0 * 8) * 2,
                   g_kerT16 + (size_t)(k0 + br0) * NPAD + n0 + bc0 * 8);
        cp_async16(bs + (br1 * B_STRIDE + bc1 * 8) * 2,
                   g_kerT16 + (size_t)(k0 + br1) * NPAD + n0 + bc1 * 8);
    };

    // prologue: prefetch STAGES-1 stages
    #pragma unroll
    for (int s = 0; s < STAGES - 1; ++s) {
        load_stage(s, s * BK);
        CP_COMMIT();
    }

    for (int i = 0; i < KITERS; ++i) {
        CP_WAIT(STAGES - 2);
        __syncthreads();

        const int s = i & (STAGES - 1);
        const uint32_t as = sb + s * STAGE_BYTES;
        const uint32_t bs = as + A_STAGE_BYTES;

        #pragma unroll
        for (int ks = 0; ks < BK; ks += 16) {
            uint32_t A[4][4];
            #pragma unroll
            for (int mf = 0; mf < 4; ++mf) {
                const int row = warp_m * 64 + mf * 16 + row8;
                ldmatrix_x4(A[mf], as + (row * A_STRIDE + ks + off8) * 2);
            }
            uint32_t Bv[4][2];
            #pragma unroll
            for (int p = 0; p < 2; ++p) {
                const int krow = ks + row8;
                const int ncol = warp_n * 32 + p * 16 + off8;
                uint32_t r[4];
                ldmatrix_x4_t(r, bs + (krow * B_STRIDE + ncol) * 2);
                Bv[2 * p][0] = r[0]; Bv[2 * p][1] = r[1];
                Bv[2 * p + 1][0] = r[2]; Bv[2 * p + 1][1] = r[3];
            }
            #pragma unroll
            for (int mf = 0; mf < 4; ++mf)
                #pragma unroll
                for (int nf = 0; nf < 4; ++nf)
                    mma_16816(acc[mf][nf], A[mf], Bv[nf]);
        }

        if (i + STAGES - 1 < KITERS)
            load_stage((i + STAGES - 1) & (STAGES - 1), (i + STAGES - 1) * BK);
        CP_COMMIT();
    }

    // ---- epilogue: direct float2 {real, imag} stores ----
    const int t_base = m0 + warp_m * 64;
    const int c_base = n0 + warp_n * 32;
    const int row_l  = lane >> 2;
    const int colp   = (lane & 3) * 2;   // even -> (real, imag) pair

    #pragma unroll
    for (int mf = 0; mf < 4; ++mf) {
        #pragma unroll
        for (int nf = 0; nf < 4; ++nf) {
            const int f = (c_base + nf * 8 + colp) >> 1;
            float* op = out + ((size_t)b * F_BINS + f) * (size_t)N_FRAMES * 2;
            const int t0 = t_base + mf * 16 + row_l;
            *reinterpret_cast<float2*>(op + (size_t)t0 * 2) =
                make_float2(acc[mf][nf][0], acc[mf][nf][1]);
            *reinterpret_cast<float2*>(op + (size_t)(t0 + 8) * 2) =
                make_float2(acc[mf][nf][2], acc[mf][nf][3]);
        }
    }
}

// ---------------------------------------------------------------------------
// Host launcher
// ---------------------------------------------------------------------------
extern "C" void kernel_launch(void* const* d_in, const int* in_sizes, int n_in,
                              void* d_out, int out_size) {
    (void)in_sizes; (void)n_in; (void)out_size;
    const float* signal = (const float*)d_in[0];   // [16, 262144] fp32
    const float* kernel = (const float*)d_in[1];   // [1026, 1024] fp32
    float* out = (float*)d_out;                    // [16, 513, 1025, 2] fp32

    // Prologue conversions
    {
        int n1 = BATCH * PADDED_LEN;
        pad_convert_kernel<<<(n1 + 255) / 256, 256>>>(signal);
        int n2 = NFFT * N_CH;
        ker_convert_kernel<<<(n2 + 255) / 256, 256>>>(kernel);
    }

    // Main GEMM
    static bool attr_set = false;
    if (!attr_set) {
        cudaFuncSetAttribute(stft_gemm,
                             cudaFuncAttributeMaxDynamicSharedMemorySize,
                             SMEM_TOTAL);
        attr_set = true;
    }
    stft_gemm<<<dim3(8, 8, BATCH), 256, SMEM_TOTAL>>>(out);

    // Exact fp32 cleanup: frame t=1024 (c' < 1024) and bin f=512 (all t)
    cleanup_last_frame<<<dim3(128, BATCH), 256>>>(signal, kernel, out);
    cleanup_last_bin<<<dim3(1025, BATCH), 64>>>(signal, kernel, out);
}